// round 12
// baseline (speedup 1.0000x reference)
#include <cuda_runtime.h>
#include <cstdint>

// self_attention_76416058130984 — GB300 sm_103a
// frames: [4, B=8, C=64, H=160, W=160] fp32 -> out: [8, 256, 160, 160] fp32
//
// Per pixel: E_ij(c) = exp(x_i[c]*x_j[c]) (symmetric, 10 unique per channel),
// denom_i = sum_{j,c} E_ij(c),  out_i[c] = (sum_j E_ij(c)*x_j[c]) / denom_i.
// No max-subtraction needed (logits bounded ~40, fp32 safe; softmax shift-invariant).
//
// R12 = R11 (72.4us: cp.async double-buffer + lane=pixel zero-SHFL mapping)
// with pipeline-bubble squeezes: TPB 4->8 (half the exposed prologues),
// st.global.cs streaming stores, last-tile barrier elision.

#define B_       8
#define C_       64
#define H_       160
#define W_       160
#define HW_      (H_*W_)            // 25600
#define WTILE    32
#define NTHREADS 256
#define TPB      8                  // tiles per block
#define NTILES   (B_*H_*(W_/WTILE)) // 6400
#define TILE_F   (4*C_*WTILE)       // 8192 floats = 32KB
#define PD_OFF   (2*TILE_F)         // pd[8 warps][4 i][32 px] = 1024 floats
#define INVD_OFF (PD_OFF + 8*4*32)  // invd[4 i][32 px] = 128 floats
#define SMEM_F   (INVD_OFF + 4*32)  // 17664 floats
#define SMEM_BYTES (SMEM_F*4)       // 70656 B -> 3 blocks/SM

__device__ __forceinline__ float ex2a(float x) {
    float y; asm("ex2.approx.f32 %0, %1;" : "=f"(y) : "f"(x)); return y;
}
__device__ __forceinline__ float rcpa(float x) {
    float y; asm("rcp.approx.f32 %0, %1;" : "=f"(y) : "f"(x)); return y;
}
__device__ __forceinline__ void cpasync16(uint32_t dst_s, const void* src_g) {
    asm volatile("cp.async.cg.shared.global [%0], [%1], 16;"
                 :: "r"(dst_s), "l"(src_g));
}
__device__ __forceinline__ void stcs4(float* p, float4 v) {
    asm volatile("st.global.cs.v4.f32 [%0], {%1,%2,%3,%4};"
                 :: "l"(p), "f"(v.x), "f"(v.y), "f"(v.z), "f"(v.w));
}

// 10 unique exps -> row sums r[i] and gated sums y[i]
__device__ __forceinline__ void attn4(const float a[4], float y[4], float r[4]) {
    const float L2E = 1.44269504f;   // log2(e)
    float b0 = a[0]*L2E, b1 = a[1]*L2E, b2 = a[2]*L2E, b3 = a[3]*L2E;
    float e00 = ex2a(a[0]*b0), e01 = ex2a(a[0]*b1), e02 = ex2a(a[0]*b2), e03 = ex2a(a[0]*b3);
    float e11 = ex2a(a[1]*b1), e12 = ex2a(a[1]*b2), e13 = ex2a(a[1]*b3);
    float e22 = ex2a(a[2]*b2), e23 = ex2a(a[2]*b3);
    float e33 = ex2a(a[3]*b3);
    r[0] = (e00+e01)+(e02+e03);
    r[1] = (e01+e11)+(e12+e13);
    r[2] = (e02+e12)+(e22+e23);
    r[3] = (e03+e13)+(e23+e33);
    y[0] = fmaf(e00,a[0], fmaf(e01,a[1], fmaf(e02,a[2], e03*a[3])));
    y[1] = fmaf(e01,a[0], fmaf(e11,a[1], fmaf(e12,a[2], e13*a[3])));
    y[2] = fmaf(e02,a[0], fmaf(e12,a[1], fmaf(e22,a[2], e23*a[3])));
    y[3] = fmaf(e03,a[0], fmaf(e13,a[1], fmaf(e23,a[2], e33*a[3])));
}

// async-copy one 32-pixel tile (256 rows x 32 floats) into smem buffer
__device__ __forceinline__ void ca_tile(uint32_t dst_s, int tid, int t,
                                        const float* __restrict__ frames) {
    const int tl = tid % (W_/WTILE);
    const int h  = (tid / (W_/WTILE)) % H_;
    const int b  = tid / ((W_/WTILE)*H_);
    const int sp = h*W_ + tl*WTILE;
    #pragma unroll
    for (int m = 0; m < 8; ++m) {
        const int f   = m*NTHREADS + t;   // 0..2047 quad index
        const int row = f >> 3;           // j*64 + c
        const int q   = f & 7;
        const int j   = row >> 6;
        const int c   = row & 63;
        cpasync16(dst_s + (uint32_t)(row*WTILE + q*4)*4u,
                  frames + ((j*B_ + b)*C_ + c)*HW_ + sp + q*4);
    }
}

__global__ void __launch_bounds__(NTHREADS)
self_attn_fused_kernel(const float* __restrict__ frames, float* __restrict__ out)
{
    extern __shared__ float s[];
    const uint32_t s_u32 = (uint32_t)__cvta_generic_to_shared(s);
    const int t    = threadIdx.x;
    const int warp = t >> 5, lane = t & 31;
    const int first = blockIdx.x * TPB;

    // prologue: prefetch tile 0
    ca_tile(s_u32, first, t, frames);
    asm volatile("cp.async.commit_group;");

    #pragma unroll 2
    for (int k = 0; k < TPB; ++k) {
        float* buf = s + (k & 1)*TILE_F;

        // prefetch tile k+1 into the other buffer, then wait for tile k
        if (k + 1 < TPB) {
            ca_tile(s_u32 + (uint32_t)(((k+1)&1)*TILE_F)*4u, first+k+1, t, frames);
            asm volatile("cp.async.commit_group;");
            asm volatile("cp.async.wait_group 1;");
        } else {
            asm volatile("cp.async.wait_group 0;");
        }
        __syncthreads();

        // ---- Phase 2a: lane = pixel, warp owns channels [8w, 8w+8)
        // accumulate local partial denominators; write unnormalized y in place
        // (warp w touches only rows {*64 + c : c in its slice} -> disjoint)
        float d[4] = {0.f, 0.f, 0.f, 0.f};
        #pragma unroll
        for (int cc = 0; cc < 8; ++cc) {
            const int c = warp*8 + cc;
            float a[4];
            #pragma unroll
            for (int j = 0; j < 4; ++j)
                a[j] = buf[(j*C_ + c)*WTILE + lane];
            float y[4], r[4];
            attn4(a, y, r);
            #pragma unroll
            for (int i = 0; i < 4; ++i) {
                d[i] += r[i];
                buf[(i*C_ + c)*WTILE + lane] = y[i];
            }
        }
        #pragma unroll
        for (int i = 0; i < 4; ++i)
            s[PD_OFF + (warp*4 + i)*32 + lane] = d[i];
        __syncthreads();

        // ---- Phase 2b: reduce partial denoms across 8 warps, one rcp each
        if (t < 128) {
            const int i = t >> 5, p = t & 31;
            float sum = 0.f;
            #pragma unroll
            for (int w = 0; w < 8; ++w)
                sum += s[PD_OFF + (w*4 + i)*32 + p];
            s[INVD_OFF + i*32 + p] = rcpa(sum);
        }
        __syncthreads();

        // ---- Phase 3: normalize + coalesced streaming store
        {
            const int tid = first + k;
            const int tl = tid % (W_/WTILE);
            const int h  = (tid / (W_/WTILE)) % H_;
            const int b  = tid / ((W_/WTILE)*H_);
            const int sp = h*W_ + tl*WTILE;
            const int row0 = t >> 3;          // 0..31
            const int q4   = (t & 7)*4;       // 0..28
            #pragma unroll
            for (int it = 0; it < 8; ++it) {
                const int row = row0 + it*32; // i*64 + c
                const int i   = row >> 6;
                const float4 iv = *reinterpret_cast<const float4*>(
                    s + INVD_OFF + i*32 + q4);
                const float* yp = buf + row*WTILE + q4;
                stcs4(out + (b*4*C_ + row)*HW_ + sp + q4,
                      make_float4(yp[0]*iv.x, yp[1]*iv.y,
                                  yp[2]*iv.z, yp[3]*iv.w));
            }
        }
        // protect buf/pd/invd reuse vs next iteration's cp.async;
        // elide on the last tile (nothing follows)
        if (k + 1 < TPB) __syncthreads();
    }
}

extern "C" void kernel_launch(void* const* d_in, const int* in_sizes, int n_in,
                              void* d_out, int out_size)
{
    const float* frames = (const float*)d_in[0];
    float* out = (float*)d_out;
    cudaFuncSetAttribute(self_attn_fused_kernel,
                         cudaFuncAttributeMaxDynamicSharedMemorySize, SMEM_BYTES);
    self_attn_fused_kernel<<<NTILES/TPB, NTHREADS, SMEM_BYTES>>>(frames, out);
}

// round 14
// speedup vs baseline: 1.0283x; 1.0283x over previous
#include <cuda_runtime.h>
#include <cstdint>

// self_attention_76416058130984 — GB300 sm_103a
// frames: [4, B=8, C=64, H=160, W=160] fp32 -> out: [8, 256, 160, 160] fp32
//
// Per pixel: E_ij(c) = exp(x_i[c]*x_j[c]) (symmetric, 10 unique per channel),
// denom_i = sum_{j,c} E_ij(c),  out_i[c] = (sum_j E_ij(c)*x_j[c]) / denom_i.
// No max-subtraction needed (logits bounded ~40, fp32 safe; softmax shift-invariant).
//
// R13 = R11 pipeline (TPB=4, cp.async double-buffer, lane=pixel mapping;
// R12's TPB=8 regressed via wave tail) with the SMEM round-trip removed:
// y stays in registers, output stored directly (lane-contiguous => coalesced
// scalar STG), Phase-3 smem re-read and one barrier per tile eliminated.

#define B_       8
#define C_       64
#define H_       160
#define W_       160
#define HW_      (H_*W_)            // 25600
#define WTILE    32
#define NTHREADS 256
#define TPB      4                  // tiles per block
#define NTILES   (B_*H_*(W_/WTILE)) // 6400
#define TILE_F   (4*C_*WTILE)       // 8192 floats = 32KB
#define PD_OFF   (2*TILE_F)         // pd[8 warps][4 i][32 px] = 1024 floats
#define INVD_OFF (PD_OFF + 8*4*32)  // invd[4 i][32 px] = 128 floats
#define SMEM_F   (INVD_OFF + 4*32)  // 17664 floats
#define SMEM_BYTES (SMEM_F*4)       // 70656 B -> 3 blocks/SM

__device__ __forceinline__ float ex2a(float x) {
    float y; asm("ex2.approx.f32 %0, %1;" : "=f"(y) : "f"(x)); return y;
}
__device__ __forceinline__ float rcpa(float x) {
    float y; asm("rcp.approx.f32 %0, %1;" : "=f"(y) : "f"(x)); return y;
}
__device__ __forceinline__ void cpasync16(uint32_t dst_s, const void* src_g) {
    asm volatile("cp.async.cg.shared.global [%0], [%1], 16;"
                 :: "r"(dst_s), "l"(src_g));
}
__device__ __forceinline__ void stcs1(float* p, float v) {
    asm volatile("st.global.cs.f32 [%0], %1;" :: "l"(p), "f"(v));
}

// 10 unique exps -> row sums r[i] and gated sums y[i]
__device__ __forceinline__ void attn4(const float a[4], float y[4], float r[4]) {
    const float L2E = 1.44269504f;   // log2(e)
    float b0 = a[0]*L2E, b1 = a[1]*L2E, b2 = a[2]*L2E, b3 = a[3]*L2E;
    float e00 = ex2a(a[0]*b0), e01 = ex2a(a[0]*b1), e02 = ex2a(a[0]*b2), e03 = ex2a(a[0]*b3);
    float e11 = ex2a(a[1]*b1), e12 = ex2a(a[1]*b2), e13 = ex2a(a[1]*b3);
    float e22 = ex2a(a[2]*b2), e23 = ex2a(a[2]*b3);
    float e33 = ex2a(a[3]*b3);
    r[0] = (e00+e01)+(e02+e03);
    r[1] = (e01+e11)+(e12+e13);
    r[2] = (e02+e12)+(e22+e23);
    r[3] = (e03+e13)+(e23+e33);
    y[0] = fmaf(e00,a[0], fmaf(e01,a[1], fmaf(e02,a[2], e03*a[3])));
    y[1] = fmaf(e01,a[0], fmaf(e11,a[1], fmaf(e12,a[2], e13*a[3])));
    y[2] = fmaf(e02,a[0], fmaf(e12,a[1], fmaf(e22,a[2], e23*a[3])));
    y[3] = fmaf(e03,a[0], fmaf(e13,a[1], fmaf(e23,a[2], e33*a[3])));
}

// async-copy one 32-pixel tile (256 rows x 32 floats) into smem buffer
__device__ __forceinline__ void ca_tile(uint32_t dst_s, int tid, int t,
                                        const float* __restrict__ frames) {
    const int tl = tid % (W_/WTILE);
    const int h  = (tid / (W_/WTILE)) % H_;
    const int b  = tid / ((W_/WTILE)*H_);
    const int sp = h*W_ + tl*WTILE;
    #pragma unroll
    for (int m = 0; m < 8; ++m) {
        const int f   = m*NTHREADS + t;   // 0..2047 quad index
        const int row = f >> 3;           // j*64 + c
        const int q   = f & 7;
        const int j   = row >> 6;
        const int c   = row & 63;
        cpasync16(dst_s + (uint32_t)(row*WTILE + q*4)*4u,
                  frames + ((j*B_ + b)*C_ + c)*HW_ + sp + q*4);
    }
}

__global__ void __launch_bounds__(NTHREADS)
self_attn_fused_kernel(const float* __restrict__ frames, float* __restrict__ out)
{
    extern __shared__ float s[];
    const uint32_t s_u32 = (uint32_t)__cvta_generic_to_shared(s);
    const int t    = threadIdx.x;
    const int warp = t >> 5, lane = t & 31;
    const int first = blockIdx.x * TPB;

    // prologue: prefetch tile 0
    ca_tile(s_u32, first, t, frames);
    asm volatile("cp.async.commit_group;");

    for (int k = 0; k < TPB; ++k) {
        const float* buf = s + (k & 1)*TILE_F;

        // prefetch tile k+1 into the other buffer, then wait for tile k.
        // Safe without an end-of-loop barrier: the pd-write barrier below
        // proves every thread finished reading its buffer before the next
        // iteration's prefetch can overwrite it.
        if (k + 1 < TPB) {
            ca_tile(s_u32 + (uint32_t)(((k+1)&1)*TILE_F)*4u, first+k+1, t, frames);
            asm volatile("cp.async.commit_group;");
            asm volatile("cp.async.wait_group 1;");
        } else {
            asm volatile("cp.async.wait_group 0;");
        }
        __syncthreads();

        // ---- Phase 2a: lane = pixel, warp owns channels [8w, 8w+8)
        // y stays in registers; only partial denominators touch smem.
        float yreg[8][4];
        float d[4] = {0.f, 0.f, 0.f, 0.f};
        #pragma unroll
        for (int cc = 0; cc < 8; ++cc) {
            const int c = warp*8 + cc;
            float a[4];
            #pragma unroll
            for (int j = 0; j < 4; ++j)
                a[j] = buf[(j*C_ + c)*WTILE + lane];
            float r[4];
            attn4(a, yreg[cc], r);
            #pragma unroll
            for (int i = 0; i < 4; ++i) d[i] += r[i];
        }
        #pragma unroll
        for (int i = 0; i < 4; ++i)
            s[PD_OFF + (warp*4 + i)*32 + lane] = d[i];
        __syncthreads();

        // ---- Phase 2b: reduce partial denoms across 8 warps, one rcp each
        if (t < 128) {
            const int i = t >> 5, p = t & 31;
            float sum = 0.f;
            #pragma unroll
            for (int w = 0; w < 8; ++w)
                sum += s[PD_OFF + (w*4 + i)*32 + p];
            s[INVD_OFF + i*32 + p] = rcpa(sum);
        }
        __syncthreads();

        // ---- Phase 3: normalize from registers, direct coalesced stores.
        // For fixed (i, c), lanes write out[...+sp+lane]: contiguous 128B.
        {
            const int tid = first + k;
            const int tl = tid % (W_/WTILE);
            const int h  = (tid / (W_/WTILE)) % H_;
            const int b  = tid / ((W_/WTILE)*H_);
            const int sp = h*W_ + tl*WTILE;
            float invD[4];
            #pragma unroll
            for (int i = 0; i < 4; ++i)
                invD[i] = s[INVD_OFF + i*32 + lane];
            float* obase = out + b*4*C_*HW_ + sp + lane;
            #pragma unroll
            for (int i = 0; i < 4; ++i) {
                #pragma unroll
                for (int cc = 0; cc < 8; ++cc) {
                    const int row = i*C_ + warp*8 + cc;
                    stcs1(obase + row*HW_, yreg[cc][i] * invD[i]);
                }
            }
        }
        // no trailing barrier needed (see comment at prefetch)
    }
}

extern "C" void kernel_launch(void* const* d_in, const int* in_sizes, int n_in,
                              void* d_out, int out_size)
{
    const float* frames = (const float*)d_in[0];
    float* out = (float*)d_out;
    cudaFuncSetAttribute(self_attn_fused_kernel,
                         cudaFuncAttributeMaxDynamicSharedMemorySize, SMEM_BYTES);
    self_attn_fused_kernel<<<NTILES/TPB, NTHREADS, SMEM_BYTES>>>(frames, out);
}

// round 15
// speedup vs baseline: 1.0361x; 1.0077x over previous
#include <cuda_runtime.h>
#include <cstdint>

// self_attention_76416058130984 — GB300 sm_103a
// frames: [4, B=8, C=64, H=160, W=160] fp32 -> out: [8, 256, 160, 160] fp32
//
// Per pixel: E_ij(c) = exp(x_i[c]*x_j[c]) (symmetric, 10 unique per channel),
// denom_i = sum_{j,c} E_ij(c),  out_i[c] = (sum_j E_ij(c)*x_j[c]) / denom_i.
// No max-subtraction needed (logits bounded ~40, fp32 safe; softmax shift-invariant).
//
// R15 = R11 pipeline (TPB=4, cp.async double-buffer, y in smem, 3 blocks/SM)
// with the cross-warp denominator reduction replaced by an intra-warp one:
// lane=(cs,p) mapping, warp owns 4 pixels x all 64 channels (stride-8 per lane),
// d reduced with 3 shfl_xor. pd array, t<128 phase and one barrier eliminated
// (4 -> 3 barriers/tile). Rotated 16B chunks keep all smem accesses
// conflict-free. R13 lesson: y stays in smem (regs <= ~80, 3 blocks/SM).

#define B_       8
#define C_       64
#define H_       160
#define W_       160
#define HW_      (H_*W_)            // 25600
#define WTILE    32
#define NTHREADS 256
#define TPB      4                  // tiles per block
#define NTILES   (B_*H_*(W_/WTILE)) // 6400
#define TILE_F   (4*C_*WTILE)       // 8192 floats = 32KB
#define INVD_OFF (2*TILE_F)         // invd[4 i][32 px] = 128 floats
#define SMEM_F   (INVD_OFF + 4*32)  // 16512 floats
#define SMEM_BYTES (SMEM_F*4)       // 66048 B -> 3 blocks/SM

__device__ __forceinline__ float ex2a(float x) {
    float y; asm("ex2.approx.f32 %0, %1;" : "=f"(y) : "f"(x)); return y;
}
__device__ __forceinline__ float rcpa(float x) {
    float y; asm("rcp.approx.f32 %0, %1;" : "=f"(y) : "f"(x)); return y;
}
__device__ __forceinline__ void cpasync16(uint32_t dst_s, const void* src_g) {
    asm volatile("cp.async.cg.shared.global [%0], [%1], 16;"
                 :: "r"(dst_s), "l"(src_g));
}
__device__ __forceinline__ void stcs4(float* p, float4 v) {
    asm volatile("st.global.cs.v4.f32 [%0], {%1,%2,%3,%4};"
                 :: "l"(p), "f"(v.x), "f"(v.y), "f"(v.z), "f"(v.w));
}

// 10 unique exps -> row sums r[i] and gated sums y[i]
__device__ __forceinline__ void attn4(const float a[4], float y[4], float r[4]) {
    const float L2E = 1.44269504f;   // log2(e)
    float b0 = a[0]*L2E, b1 = a[1]*L2E, b2 = a[2]*L2E, b3 = a[3]*L2E;
    float e00 = ex2a(a[0]*b0), e01 = ex2a(a[0]*b1), e02 = ex2a(a[0]*b2), e03 = ex2a(a[0]*b3);
    float e11 = ex2a(a[1]*b1), e12 = ex2a(a[1]*b2), e13 = ex2a(a[1]*b3);
    float e22 = ex2a(a[2]*b2), e23 = ex2a(a[2]*b3);
    float e33 = ex2a(a[3]*b3);
    r[0] = (e00+e01)+(e02+e03);
    r[1] = (e01+e11)+(e12+e13);
    r[2] = (e02+e12)+(e22+e23);
    r[3] = (e03+e13)+(e23+e33);
    y[0] = fmaf(e00,a[0], fmaf(e01,a[1], fmaf(e02,a[2], e03*a[3])));
    y[1] = fmaf(e01,a[0], fmaf(e11,a[1], fmaf(e12,a[2], e13*a[3])));
    y[2] = fmaf(e02,a[0], fmaf(e12,a[1], fmaf(e22,a[2], e23*a[3])));
    y[3] = fmaf(e03,a[0], fmaf(e13,a[1], fmaf(e23,a[2], e33*a[3])));
}

// async-copy one 32-pixel tile (256 rows x 32 floats) into smem buffer.
// 16B chunk q of row r is stored at chunk ((q + (r&7)) & 7): per-row rotation
// makes the (cs,p)-lane accesses in Phase 2a conflict-free.
__device__ __forceinline__ void ca_tile(uint32_t dst_s, int tid, int t,
                                        const float* __restrict__ frames) {
    const int tl = tid % (W_/WTILE);
    const int h  = (tid / (W_/WTILE)) % H_;
    const int b  = tid / ((W_/WTILE)*H_);
    const int sp = h*W_ + tl*WTILE;
    #pragma unroll
    for (int m = 0; m < 8; ++m) {
        const int f   = m*NTHREADS + t;   // 0..2047 quad index
        const int row = f >> 3;           // j*64 + c
        const int q   = f & 7;
        const int j   = row >> 6;
        const int c   = row & 63;
        const int sc  = (q + (row & 7)) & 7;   // rotated chunk
        cpasync16(dst_s + (uint32_t)(row*WTILE + sc*4)*4u,
                  frames + ((j*B_ + b)*C_ + c)*HW_ + sp + q*4);
    }
}

__global__ void __launch_bounds__(NTHREADS)
self_attn_fused_kernel(const float* __restrict__ frames, float* __restrict__ out)
{
    extern __shared__ float s[];
    const uint32_t s_u32 = (uint32_t)__cvta_generic_to_shared(s);
    const int t    = threadIdx.x;
    const int warp = t >> 5, lane = t & 31;
    const int cs   = lane >> 2;           // channel class 0..7
    const int p    = lane & 3;            // pixel-in-group
    const int px   = warp*4 + p;          // logical pixel 0..31
    // stored column for (this row's class == cs) rows, logical chunk = warp:
    const int col  = ((warp + cs) & 7)*4 + p;
    const int first = blockIdx.x * TPB;

    // prologue: prefetch tile 0
    ca_tile(s_u32, first, t, frames);
    asm volatile("cp.async.commit_group;");

    for (int k = 0; k < TPB; ++k) {
        float* buf = s + (k & 1)*TILE_F;

        // prefetch tile k+1 into the other buffer, then wait for tile k
        if (k + 1 < TPB) {
            ca_tile(s_u32 + (uint32_t)(((k+1)&1)*TILE_F)*4u, first+k+1, t, frames);
            asm volatile("cp.async.commit_group;");
            asm volatile("cp.async.wait_group 1;");
        } else {
            asm volatile("cp.async.wait_group 0;");
        }
        __syncthreads();

        // ---- Phase 2a: warp owns pixels [4w,4w+4) x all 64 channels.
        // Lane (cs,p): channels {cs+8k}, pixel px. Per channel: read a[4],
        // compute, accumulate d, overwrite the same 4 words with y (per-lane
        // in-place, no cross-lane hazard). All accesses hit bank
        // ((warp+cs)&7)*4+p — distinct per lane -> conflict-free.
        float d[4] = {0.f, 0.f, 0.f, 0.f};
        #pragma unroll
        for (int kk = 0; kk < 8; ++kk) {
            const int c = cs + 8*kk;
            float a[4];
            #pragma unroll
            for (int j = 0; j < 4; ++j)
                a[j] = buf[(j*C_ + c)*WTILE + col];
            float y[4], r[4];
            attn4(a, y, r);
            #pragma unroll
            for (int i = 0; i < 4; ++i) {
                d[i] += r[i];
                buf[(i*C_ + c)*WTILE + col] = y[i];
            }
        }
        // intra-warp denominator reduction over cs (masks 4,8,16)
        #pragma unroll
        for (int m = 4; m <= 16; m <<= 1) {
            #pragma unroll
            for (int i = 0; i < 4; ++i)
                d[i] += __shfl_xor_sync(0xffffffffu, d[i], m);
        }
        if (cs == 0) {
            #pragma unroll
            for (int i = 0; i < 4; ++i)
                s[INVD_OFF + i*32 + px] = rcpa(d[i]);
        }
        __syncthreads();

        // ---- Phase 3: cooperative normalize + coalesced streaming store
        {
            const int tid = first + k;
            const int tl = tid % (W_/WTILE);
            const int h  = (tid / (W_/WTILE)) % H_;
            const int b  = tid / ((W_/WTILE)*H_);
            const int sp = h*W_ + tl*WTILE;
            const int row0 = t >> 3;          // 0..31
            const int qc   = t & 7;           // logical chunk 0..7
            #pragma unroll
            for (int it = 0; it < 8; ++it) {
                const int row = row0 + it*32; // i*64 + c
                const int i   = row >> 6;
                const int sc  = (qc + (row & 7)) & 7;  // stored chunk
                const float4 iv = *reinterpret_cast<const float4*>(
                    s + INVD_OFF + i*32 + qc*4);
                const float* yp = buf + row*WTILE + sc*4;
                stcs4(out + (b*4*C_ + row)*HW_ + sp + qc*4,
                      make_float4(yp[0]*iv.x, yp[1]*iv.y,
                                  yp[2]*iv.z, yp[3]*iv.w));
            }
        }
        // guard buf reuse vs next iteration's prefetch; elide on last tile
        if (k + 1 < TPB) __syncthreads();
    }
}

extern "C" void kernel_launch(void* const* d_in, const int* in_sizes, int n_in,
                              void* d_out, int out_size)
{
    const float* frames = (const float*)d_in[0];
    float* out = (float*)d_out;
    cudaFuncSetAttribute(self_attn_fused_kernel,
                         cudaFuncAttributeMaxDynamicSharedMemorySize, SMEM_BYTES);
    self_attn_fused_kernel<<<NTILES/TPB, NTHREADS, SMEM_BYTES>>>(frames, out);
}